// round 12
// baseline (speedup 1.0000x reference)
#include <cuda_runtime.h>
#include <cstdint>

// MXFP6 quant-dequant, straight-through forward => output = dequant(quant(x)).
// Blocks of 32 contiguous floats share a power-of-two scale = 2^floor(log2(max|x|, clamp 1e-8)).
//
// Exponent-byte trick: only the exponent field of the block max matters;
// pack 4 items' exponent bytes into one u32, 3x SHFL + __vmaxu4 reduce
// (8 lanes x 4 elems = one 32-elem block).
//
// R11: persistent grid-stride kernel with register double-buffering.
// Burst-style kernels plateau at ~75% DRAM because each thread's loads all
// drain before its compute/store phase (duty-cycle gap). Here, while tile t
// is being reduced/stored, the loads for tile t+stride are already in
// flight -> sustained MLP. Grid = 592 CTAs (148 SMs x 4 resident), 8192
// full 16KB tiles, no bounds checks in the steady state.

#define THREADS 256
#define VPT 4                    // float4 per thread per tile
#define TILE (THREADS * VPT)     // 1024 float4 = 16 KB per tile

__global__ __launch_bounds__(THREADS, 4)
void mxfp6_qdq_kernel(const float* __restrict__ x,
                      float* __restrict__ out,
                      int ntiles)
{
    const float4* __restrict__ xin = reinterpret_cast<const float4*>(x);
    float4* __restrict__ o = reinterpret_cast<float4*>(out);

    int tile = blockIdx.x;
    const int stride = gridDim.x;
    if (tile >= ntiles) return;

    const float M = 15.0f;
    const float invM = 1.0f / 15.0f;

    // Prologue: load first tile
    float4 cur[VPT];
    {
        const int b = tile * TILE + threadIdx.x;
        #pragma unroll
        for (int k = 0; k < VPT; k++)
            cur[k] = __ldcs(xin + b + k * THREADS);
    }

    while (true) {
        const int ntile = tile + stride;
        const bool has_next = ntile < ntiles;

        // Prefetch next tile BEFORE computing current one; these loads stay
        // in flight across the reduction/store below (independent registers).
        float4 nxt[VPT];
        if (has_next) {
            const int nb = ntile * TILE + threadIdx.x;
            #pragma unroll
            for (int k = 0; k < VPT; k++)
                nxt[k] = __ldcs(xin + nb + k * THREADS);
        }

        // ---- reduce: per-item |max| -> exponent byte, packed SIMD max ----
        unsigned s[VPT];
        #pragma unroll
        for (int k = 0; k < VPT; k++) {
            float m = fmaxf(fmaxf(fabsf(cur[k].x), fabsf(cur[k].y)),
                            fmaxf(fabsf(cur[k].z), fabsf(cur[k].w)));
            s[k] = __float_as_uint(m) << 1;   // top byte == exponent field
        }
        unsigned lo = __byte_perm(s[0], s[1], 0x0073);
        unsigned hi = __byte_perm(s[2], s[3], 0x0073);
        unsigned w  = __byte_perm(lo, hi, 0x5410);

        // 8 lanes cover one 32-elem block per item -> 3-step byte-max reduce
        w = __vmaxu4(w, __shfl_xor_sync(0xffffffffu, w, 1));
        w = __vmaxu4(w, __shfl_xor_sync(0xffffffffu, w, 2));
        w = __vmaxu4(w, __shfl_xor_sync(0xffffffffu, w, 4));

        // 1e-8 clamp == exponent-field clamp at 100 (0x64)
        w = __vmaxu4(w, 0x64646464u);

        // ---- quant-dequant + store current tile ----
        const int b = tile * TILE + threadIdx.x;
        #pragma unroll
        for (int k = 0; k < VPT; k++) {
            unsigned e = __byte_perm(w, 0, k) & 0xFFu;
            float scale     = __int_as_float((int)(e << 23));
            float inv_scale = __int_as_float((int)((254u - e) << 23));
            float f1 = inv_scale * M;   // exact: power-of-two * 15
            float f2 = invM * scale;    // same rounding as (q/15)*scale

            float4 v = cur[k], r;
            r.x = fminf(fmaxf(rintf(v.x * f1), -M), M) * f2;
            r.y = fminf(fmaxf(rintf(v.y * f1), -M), M) * f2;
            r.z = fminf(fmaxf(rintf(v.z * f1), -M), M) * f2;
            r.w = fminf(fmaxf(rintf(v.w * f1), -M), M) * f2;

            __stcs(o + b + k * THREADS, r);
        }

        if (!has_next) break;
        #pragma unroll
        for (int k = 0; k < VPT; k++) cur[k] = nxt[k];
        tile = ntile;
    }
}

extern "C" void kernel_launch(void* const* d_in, const int* in_sizes, int n_in,
                              void* d_out, int out_size)
{
    const float* x = (const float*)d_in[0];
    float* out = (float*)d_out;
    int n = in_sizes[0];              // 33,554,432
    int n4 = n >> 2;                  // 8,388,608 float4s
    int ntiles = n4 / TILE;           // 8192 exactly (n divisible by 32768)

    int blocks = 148 * 4;             // persistent: exactly-resident grid
    if (blocks > ntiles) blocks = ntiles;
    mxfp6_qdq_kernel<<<blocks, THREADS>>>(x, out, ntiles);
}

// round 13
// speedup vs baseline: 1.0705x; 1.0705x over previous
#include <cuda_runtime.h>
#include <cstdint>

// MXFP6 quant-dequant, straight-through forward => output = dequant(quant(x)).
// Blocks of 32 contiguous floats share a power-of-two scale = 2^floor(log2(max|x|, clamp 1e-8)).
//
// Exponent-byte trick: only the exponent field of the block max matters;
// pack 4 items' exponent bytes per u32, reduce the 8-lane group with
// 3 SHFL + __vmaxu4 per packed word (6 SHFLs total for 8 blocks).
//
// R12: consolidation on the proven-best R4 shape. Session findings:
//  - DRAM traffic invariant ~212MB across all configs; 5.9-6.0 TB/s is the
//    mixed read+write ceiling -> R4's 35.5us kernel IS the roofline.
//  - L2 eviction hints (evict-normal/evict_last/.cs splits) are inert here.
//  - LDG.256 costs 2x L1 wavefronts: regression. Keep LDG.128.
//  - Register caps make ptxas re-materialize addresses and serialize the
//    load batch: regression. Keep __launch_bounds__(256,4), ~52 regs.
//  - Only surviving micro-opt: hoisted exact f1/f2 factors (-2 FMUL/elem).

#define ITEMS 8
#define THREADS 256

__global__ __launch_bounds__(THREADS, 4)
void mxfp6_qdq_kernel(const float* __restrict__ x,
                      float* __restrict__ out,
                      int n4)
{
    const int base = blockIdx.x * (THREADS * ITEMS) + threadIdx.x;

    float4 v[ITEMS];

    const bool full = (base + (ITEMS - 1) * THREADS) < n4;

    if (full) {
        // Batched independent LDG.128 -> 8 loads in flight per thread
        #pragma unroll
        for (int k = 0; k < ITEMS; k++)
            v[k] = __ldcs(reinterpret_cast<const float4*>(x) + base + k * THREADS);
    } else {
        #pragma unroll
        for (int k = 0; k < ITEMS; k++) {
            int idx = base + k * THREADS;
            if (idx < n4) v[k] = __ldcs(reinterpret_cast<const float4*>(x) + idx);
            else          v[k] = make_float4(0.f, 0.f, 0.f, 0.f);
        }
    }

    // Per-item local max of |.|; keep only the exponent byte (bits<<1 top byte)
    unsigned s[ITEMS];
    #pragma unroll
    for (int k = 0; k < ITEMS; k++) {
        float m = fmaxf(fmaxf(fabsf(v[k].x), fabsf(v[k].y)),
                        fmaxf(fabsf(v[k].z), fabsf(v[k].w)));
        s[k] = __float_as_uint(m) << 1;
    }

    // Pack exponent bytes: w0 = items 0..3, w1 = items 4..7
    unsigned w0, w1;
    {
        unsigned lo = __byte_perm(s[0], s[1], 0x0073);
        unsigned hi = __byte_perm(s[2], s[3], 0x0073);
        w0 = __byte_perm(lo, hi, 0x5410);
        lo = __byte_perm(s[4], s[5], 0x0073);
        hi = __byte_perm(s[6], s[7], 0x0073);
        w1 = __byte_perm(lo, hi, 0x5410);
    }

    // Two interleaved 3-step SIMD byte-max reductions over the 8-lane group
    #pragma unroll
    for (int st = 1; st <= 4; st <<= 1) {
        unsigned t0 = __shfl_xor_sync(0xffffffffu, w0, st);
        unsigned t1 = __shfl_xor_sync(0xffffffffu, w1, st);
        w0 = __vmaxu4(w0, t0);
        w1 = __vmaxu4(w1, t1);
    }

    // 1e-8 clamp == exponent-field clamp at 100 (0x64)
    w0 = __vmaxu4(w0, 0x64646464u);
    w1 = __vmaxu4(w1, 0x64646464u);

    const float M = 15.0f;
    const float invM = 1.0f / 15.0f;

    if (full) {
        #pragma unroll
        for (int k = 0; k < ITEMS; k++) {
            unsigned e = __byte_perm(k < 4 ? w0 : w1, 0, k & 3);
            float scale     = __int_as_float((int)(e << 23));
            float inv_scale = __int_as_float((int)((254u - e) << 23));
            float f1 = inv_scale * M;   // exact: power-of-two * 15
            float f2 = invM * scale;    // same mantissa rounding as (q/15)*scale

            float4 o;
            o.x = fminf(fmaxf(rintf(v[k].x * f1), -M), M) * f2;
            o.y = fminf(fmaxf(rintf(v[k].y * f1), -M), M) * f2;
            o.z = fminf(fmaxf(rintf(v[k].z * f1), -M), M) * f2;
            o.w = fminf(fmaxf(rintf(v[k].w * f1), -M), M) * f2;

            __stcs(reinterpret_cast<float4*>(out) + base + k * THREADS, o);
        }
    } else {
        #pragma unroll
        for (int k = 0; k < ITEMS; k++) {
            int idx = base + k * THREADS;
            if (idx < n4) {
                unsigned e = __byte_perm(k < 4 ? w0 : w1, 0, k & 3);
                float scale     = __int_as_float((int)(e << 23));
                float inv_scale = __int_as_float((int)((254u - e) << 23));
                float f1 = inv_scale * M;
                float f2 = invM * scale;

                float4 o;
                o.x = fminf(fmaxf(rintf(v[k].x * f1), -M), M) * f2;
                o.y = fminf(fmaxf(rintf(v[k].y * f1), -M), M) * f2;
                o.z = fminf(fmaxf(rintf(v[k].z * f1), -M), M) * f2;
                o.w = fminf(fmaxf(rintf(v[k].w * f1), -M), M) * f2;

                __stcs(reinterpret_cast<float4*>(out) + idx, o);
            }
        }
    }
}

extern "C" void kernel_launch(void* const* d_in, const int* in_sizes, int n_in,
                              void* d_out, int out_size)
{
    const float* x = (const float*)d_in[0];
    float* out = (float*)d_out;
    int n = in_sizes[0];             // 33,554,432
    int n4 = n >> 2;                 // 8,388,608 float4s
    int blocks = (n4 + THREADS * ITEMS - 1) / (THREADS * ITEMS);  // 4096
    mxfp6_qdq_kernel<<<blocks, THREADS>>>(x, out, n4);
}